// round 1
// baseline (speedup 1.0000x reference)
#include <cuda_runtime.h>
#include <cstdint>

#define B_  32
#define T_  512
#define H_  1024
#define G4_ 4096
#define M_  (B_ * T_)   // 16384

// ---------------- static device scratch (no allocations allowed) ----------------
__device__ float g_xg[(size_t)M_ * G4_];     // 256 MB: gate preactivations for current layer
__device__ float g_h0seq[(size_t)M_ * H_];   // 64 MB: layer-0 output sequence
__device__ float g_hbuf[2][B_ * H_];         // double-buffered recurrent h (tf32-rounded)
__device__ unsigned g_arrive;
__device__ unsigned g_gen;

// ---------------- helpers ----------------
__device__ __forceinline__ float f2tf32(float x) {
    uint32_t r;
    asm("cvt.rna.tf32.f32 %0, %1;" : "=r"(r) : "f"(x));
    return __uint_as_float(r);
}

__device__ __forceinline__ void mma_tf32(float& c0, float& c1, float& c2, float& c3,
                                         uint32_t a0, uint32_t a1, uint32_t a2, uint32_t a3,
                                         uint32_t b0, uint32_t b1) {
    asm volatile(
        "mma.sync.aligned.m16n8k8.row.col.f32.tf32.tf32.f32 "
        "{%0,%1,%2,%3},{%4,%5,%6,%7},{%8,%9},{%0,%1,%2,%3};"
        : "+f"(c0), "+f"(c1), "+f"(c2), "+f"(c3)
        : "r"(a0), "r"(a1), "r"(a2), "r"(a3), "r"(b0), "r"(b1));
}

__device__ __forceinline__ float sigm(float x) {
    return 1.0f / (1.0f + __expf(-x));
}

__device__ __forceinline__ void grid_barrier(unsigned nb) {
    __syncthreads();
    if (threadIdx.x == 0) {
        __threadfence();
        volatile unsigned* genp = &g_gen;
        unsigned gen = *genp;
        if (atomicAdd(&g_arrive, 1u) == nb - 1) {
            g_arrive = 0;
            __threadfence();
            *genp = gen + 1;
        } else {
            while (*genp == gen) { }
            __threadfence();
        }
    }
    __syncthreads();
}

// ---------------- big GEMM: C[M,4096] = A[M,1024] * W[4096,1024]^T + bias ----------------
// CTA tile 128x128, K-chunk 16, 8 warps (2M x 4N), warp tile 64x32, tf32 mma.
#define GA_STRIDE 20   // 16 + 4 pad, keeps 16B alignment (20*4=80)

__global__ __launch_bounds__(256, 2)
void gemm_xg_kernel(const float* __restrict__ A,   // [M,1024] row-major
                    const float* __restrict__ W,   // [4096,1024] row-major
                    const float* __restrict__ b0,
                    const float* __restrict__ b1,
                    float* __restrict__ C)         // [M,4096]
{
    __shared__ float Ash[128 * GA_STRIDE];
    __shared__ float Bsh[128 * GA_STRIDE];

    const int tid  = threadIdx.x;
    const int wid  = tid >> 5, lane = tid & 31;
    const int g    = lane >> 2, t = lane & 3;
    const int wm   = wid & 1, wn = wid >> 1;
    const int cm   = blockIdx.y * 128;
    const int cn   = blockIdx.x * 128;

    float acc[4][4][4];
    #pragma unroll
    for (int i = 0; i < 4; i++)
        #pragma unroll
        for (int j = 0; j < 4; j++)
            #pragma unroll
            for (int q = 0; q < 4; q++) acc[i][j][q] = 0.0f;

    const int r0 = tid >> 2;   // 0..63
    const int q0 = tid & 3;    // which float4 in the 16-wide K chunk

    const float* Ag = A + (size_t)cm * 1024;
    const float* Bg = W + (size_t)cn * 1024;

    for (int kk = 0; kk < 1024; kk += 16) {
        float4 av0 = *(const float4*)(Ag + (size_t)r0 * 1024 + kk + 4 * q0);
        float4 av1 = *(const float4*)(Ag + (size_t)(r0 + 64) * 1024 + kk + 4 * q0);
        float4 bv0 = *(const float4*)(Bg + (size_t)r0 * 1024 + kk + 4 * q0);
        float4 bv1 = *(const float4*)(Bg + (size_t)(r0 + 64) * 1024 + kk + 4 * q0);
        __syncthreads();   // previous iteration's compute done reading smem
        {
            float4 w;
            w.x = f2tf32(av0.x); w.y = f2tf32(av0.y); w.z = f2tf32(av0.z); w.w = f2tf32(av0.w);
            *(float4*)(Ash + r0 * GA_STRIDE + 4 * q0) = w;
            w.x = f2tf32(av1.x); w.y = f2tf32(av1.y); w.z = f2tf32(av1.z); w.w = f2tf32(av1.w);
            *(float4*)(Ash + (r0 + 64) * GA_STRIDE + 4 * q0) = w;
            w.x = f2tf32(bv0.x); w.y = f2tf32(bv0.y); w.z = f2tf32(bv0.z); w.w = f2tf32(bv0.w);
            *(float4*)(Bsh + r0 * GA_STRIDE + 4 * q0) = w;
            w.x = f2tf32(bv1.x); w.y = f2tf32(bv1.y); w.z = f2tf32(bv1.z); w.w = f2tf32(bv1.w);
            *(float4*)(Bsh + (r0 + 64) * GA_STRIDE + 4 * q0) = w;
        }
        __syncthreads();

        #pragma unroll
        for (int kc = 0; kc < 16; kc += 8) {
            uint32_t af[4][4];
            uint32_t bf[4][2];
            #pragma unroll
            for (int mt = 0; mt < 4; mt++) {
                int rb = wm * 64 + mt * 16;
                af[mt][0] = __float_as_uint(Ash[(rb + g)     * GA_STRIDE + kc + t]);
                af[mt][1] = __float_as_uint(Ash[(rb + g + 8) * GA_STRIDE + kc + t]);
                af[mt][2] = __float_as_uint(Ash[(rb + g)     * GA_STRIDE + kc + t + 4]);
                af[mt][3] = __float_as_uint(Ash[(rb + g + 8) * GA_STRIDE + kc + t + 4]);
            }
            #pragma unroll
            for (int nt = 0; nt < 4; nt++) {
                int nb = wn * 32 + nt * 8 + g;
                bf[nt][0] = __float_as_uint(Bsh[nb * GA_STRIDE + kc + t]);
                bf[nt][1] = __float_as_uint(Bsh[nb * GA_STRIDE + kc + t + 4]);
            }
            #pragma unroll
            for (int mt = 0; mt < 4; mt++)
                #pragma unroll
                for (int nt = 0; nt < 4; nt++)
                    mma_tf32(acc[mt][nt][0], acc[mt][nt][1], acc[mt][nt][2], acc[mt][nt][3],
                             af[mt][0], af[mt][1], af[mt][2], af[mt][3],
                             bf[nt][0], bf[nt][1]);
        }
    }

    // epilogue: add bias, write fp32
    #pragma unroll
    for (int mt = 0; mt < 4; mt++) {
        #pragma unroll
        for (int nt = 0; nt < 4; nt++) {
            int m = cm + wm * 64 + mt * 16 + g;
            int n = cn + wn * 32 + nt * 8 + 2 * t;
            float bs0 = b0[n] + b1[n];
            float bs1 = b0[n + 1] + b1[n + 1];
            float2 v0 = make_float2(acc[mt][nt][0] + bs0, acc[mt][nt][1] + bs1);
            float2 v1 = make_float2(acc[mt][nt][2] + bs0, acc[mt][nt][3] + bs1);
            *(float2*)(C + (size_t)m * G4_ + n) = v0;
            *(float2*)(C + (size_t)(m + 8) * G4_ + n) = v1;
        }
    }
}

// ---------------- persistent LSTM scan ----------------
// 128 blocks, block b owns h-columns [8b, 8b+8) for all 4 gates.
// Shared: Whh slice [32 rows][1024] (tf32-rounded, stride 1028),
//         h chunk [32][128] (stride 136), gate buffer [4][32][8].
#define W_STRIDE 1028
#define H_STRIDE 136
#define SCAN_SMEM ((32 * W_STRIDE + 32 * H_STRIDE + 4 * 32 * 8) * 4)
#define NBLK 128

__global__ __launch_bounds__(256, 1)
void lstm_scan_kernel(const float* __restrict__ xg,     // [M, 4096]
                      const float* __restrict__ Whh,    // [4096, 1024]
                      const float* __restrict__ resid,  // [M, 1024] or nullptr
                      float* __restrict__ outseq)       // [M, 1024]
{
    extern __shared__ float smem[];
    float* Wsh = smem;                          // 32 x W_STRIDE
    float* Hsh = smem + 32 * W_STRIDE;          // 32 x H_STRIDE
    float* Gsh = Hsh + 32 * H_STRIDE;           // 4 x 32 x 8

    const int tid  = threadIdx.x;
    const int bid  = blockIdx.x;
    const int wid  = tid >> 5, lane = tid & 31;
    const int g    = lane >> 2, t = lane & 3;
    const int gate = wid & 3;        // 0..3 = i,f,g,o
    const int mh   = wid >> 2;       // which 16-row half of the 32 batch rows

    // ---- fill Whh slice into shared (tf32-rounded) ----
    for (int r = 0; r < 32; r++) {
        int grow = (r >> 3) * 1024 + bid * 8 + (r & 7);
        float4 v = *(const float4*)(Whh + (size_t)grow * 1024 + tid * 4);
        float4 w;
        w.x = f2tf32(v.x); w.y = f2tf32(v.y); w.z = f2tf32(v.z); w.w = f2tf32(v.w);
        *(float4*)(Wsh + r * W_STRIDE + tid * 4) = w;
    }

    // elementwise mapping: thread -> (batch row, local h col)
    const int erow = tid >> 3;         // 0..31
    const int ecol = tid & 7;          // 0..7
    const int hcol = bid * 8 + ecol;

    // zero the initial h buffer slice; c state lives in a register
    g_hbuf[0][erow * H_ + hcol] = 0.0f;
    float c_state = 0.0f;
    grid_barrier(NBLK);

    int p = 0;
    for (int tstep = 0; tstep < T_; tstep++) {
        // prefetch xg + residual for this step (hidden behind recurrent GEMM)
        const size_t mrow = (size_t)erow * T_ + tstep;
        float xgv0 = xg[mrow * G4_ + 0    + hcol];
        float xgv1 = xg[mrow * G4_ + 1024 + hcol];
        float xgv2 = xg[mrow * G4_ + 2048 + hcol];
        float xgv3 = xg[mrow * G4_ + 3072 + hcol];
        float rv = 0.0f;
        if (resid) rv = resid[mrow * H_ + hcol];

        const float* hsrc = g_hbuf[p];

        float c0 = 0.0f, c1 = 0.0f, c2 = 0.0f, c3 = 0.0f;

        // preload chunk 0 into regs, then smem
        float4 v[4];
        #pragma unroll
        for (int i = 0; i < 4; i++) {
            int id = i * 256 + tid;
            int hr = id >> 5, k4 = id & 31;
            v[i] = __ldcg((const float4*)(hsrc + hr * H_ + k4 * 4));
        }
        #pragma unroll
        for (int i = 0; i < 4; i++) {
            int id = i * 256 + tid;
            int hr = id >> 5, k4 = id & 31;
            *(float4*)(Hsh + hr * H_STRIDE + k4 * 4) = v[i];
        }
        __syncthreads();

        for (int cch = 0; cch < 8; cch++) {
            if (cch < 7) {
                #pragma unroll
                for (int i = 0; i < 4; i++) {
                    int id = i * 256 + tid;
                    int hr = id >> 5, k4 = id & 31;
                    v[i] = __ldcg((const float4*)(hsrc + hr * H_ + (cch + 1) * 128 + k4 * 4));
                }
            }
            const int kwbase = cch * 128;
            #pragma unroll
            for (int kc = 0; kc < 128; kc += 8) {
                uint32_t a0 = __float_as_uint(Hsh[(mh * 16 + g)     * H_STRIDE + kc + t]);
                uint32_t a1 = __float_as_uint(Hsh[(mh * 16 + g + 8) * H_STRIDE + kc + t]);
                uint32_t a2 = __float_as_uint(Hsh[(mh * 16 + g)     * H_STRIDE + kc + t + 4]);
                uint32_t a3 = __float_as_uint(Hsh[(mh * 16 + g + 8) * H_STRIDE + kc + t + 4]);
                uint32_t b0 = __float_as_uint(Wsh[(gate * 8 + g) * W_STRIDE + kwbase + kc + t]);
                uint32_t b1 = __float_as_uint(Wsh[(gate * 8 + g) * W_STRIDE + kwbase + kc + t + 4]);
                mma_tf32(c0, c1, c2, c3, a0, a1, a2, a3, b0, b1);
            }
            __syncthreads();
            if (cch < 7) {
                #pragma unroll
                for (int i = 0; i < 4; i++) {
                    int id = i * 256 + tid;
                    int hr = id >> 5, k4 = id & 31;
                    *(float4*)(Hsh + hr * H_STRIDE + k4 * 4) = v[i];
                }
                __syncthreads();
            }
        }

        // gates -> shared for elementwise redistribution
        Gsh[gate * 256 + (mh * 16 + g)     * 8 + 2 * t]     = c0;
        Gsh[gate * 256 + (mh * 16 + g)     * 8 + 2 * t + 1] = c1;
        Gsh[gate * 256 + (mh * 16 + g + 8) * 8 + 2 * t]     = c2;
        Gsh[gate * 256 + (mh * 16 + g + 8) * 8 + 2 * t + 1] = c3;
        __syncthreads();

        // elementwise LSTM cell (thread owns (erow, hcol)); tid == erow*8+ecol
        float gi = Gsh[0   + tid] + xgv0;
        float gf = Gsh[256 + tid] + xgv1;
        float gg = Gsh[512 + tid] + xgv2;
        float go = Gsh[768 + tid] + xgv3;
        float iv = sigm(gi);
        float fv = sigm(gf);
        float gv = tanhf(gg);
        float ov = sigm(go);
        c_state = fv * c_state + iv * gv;
        float hval = ov * tanhf(c_state);

        g_hbuf[1 - p][erow * H_ + hcol] = f2tf32(hval);   // recurrent copy, pre-rounded
        outseq[mrow * H_ + hcol] = hval + rv;             // full-precision output (+residual)

        grid_barrier(NBLK);
        p ^= 1;
    }
}

// ---------------- launch ----------------
extern "C" void kernel_launch(void* const* d_in, const int* in_sizes, int n_in,
                              void* d_out, int out_size) {
    const float* x    = (const float*)d_in[0];
    const float* Wih0 = (const float*)d_in[1];
    const float* Whh0 = (const float*)d_in[2];
    const float* bih0 = (const float*)d_in[3];
    const float* bhh0 = (const float*)d_in[4];
    const float* Wih1 = (const float*)d_in[5];
    const float* Whh1 = (const float*)d_in[6];
    const float* bih1 = (const float*)d_in[7];
    const float* bhh1 = (const float*)d_in[8];
    float* out = (float*)d_out;

    cudaFuncSetAttribute(lstm_scan_kernel,
                         cudaFuncAttributeMaxDynamicSharedMemorySize, SCAN_SMEM);

    void* p;
    cudaGetSymbolAddress(&p, g_xg);    float* xg = (float*)p;
    cudaGetSymbolAddress(&p, g_h0seq); float* h0 = (float*)p;

    dim3 gg(32, 128);  // (N tiles, M tiles)

    // layer 0
    gemm_xg_kernel<<<gg, 256>>>(x, Wih0, bih0, bhh0, xg);
    lstm_scan_kernel<<<NBLK, 256, SCAN_SMEM>>>(xg, Whh0, nullptr, h0);
    // layer 1 (+ residual into final out)
    gemm_xg_kernel<<<gg, 256>>>(h0, Wih1, bih1, bhh1, xg);
    lstm_scan_kernel<<<NBLK, 256, SCAN_SMEM>>>(xg, Whh1, h0, out);
}

// round 3
// speedup vs baseline: 1.8373x; 1.8373x over previous
#include <cuda_runtime.h>
#include <cstdint>

#define B_  32
#define T_  512
#define H_  1024
#define G4_ 4096
#define M_  (B_ * T_)   // 16384
#define NBLK 128
#define NTHR 512

// ---------------- static device scratch (no allocations allowed) ----------------
__device__ float g_xg[(size_t)M_ * G4_];     // gate preactivations for current layer
__device__ float g_h0seq[(size_t)M_ * H_];   // layer-0 output sequence (normal layout)
// frag-permuted recurrent h, double buffered: [buf][s(128)][mt(2)][lane(32)][r(4)]
__device__ float g_hA[2][32768];
__device__ unsigned g_arrive;

// ---------------- helpers ----------------
__device__ __forceinline__ float f2tf32(float x) {
    uint32_t r;
    asm("cvt.rna.tf32.f32 %0, %1;" : "=r"(r) : "f"(x));
    return __uint_as_float(r);
}

__device__ __forceinline__ void mma_tf32(float& c0, float& c1, float& c2, float& c3,
                                         uint32_t a0, uint32_t a1, uint32_t a2, uint32_t a3,
                                         uint32_t b0, uint32_t b1) {
    asm volatile(
        "mma.sync.aligned.m16n8k8.row.col.f32.tf32.tf32.f32 "
        "{%0,%1,%2,%3},{%4,%5,%6,%7},{%8,%9},{%0,%1,%2,%3};"
        : "+f"(c0), "+f"(c1), "+f"(c2), "+f"(c3)
        : "r"(a0), "r"(a1), "r"(a2), "r"(a3), "r"(b0), "r"(b1));
}

__device__ __forceinline__ float sigm(float x) {
    return 1.0f / (1.0f + __expf(-x));
}

// release/acquire grid barrier on a monotonic counter (reset between launches)
__device__ __forceinline__ void grid_barrier(unsigned target) {
    __syncthreads();
    if (threadIdx.x == 0) {
        unsigned old;
        asm volatile("atom.release.gpu.global.add.u32 %0, [%1], 1;"
                     : "=r"(old) : "l"(&g_arrive) : "memory");
        unsigned v;
        do {
            asm volatile("ld.acquire.gpu.global.u32 %0, [%1];"
                         : "=r"(v) : "l"(&g_arrive) : "memory");
        } while (v < target);
    }
    __syncthreads();
}

// ---------------- big GEMM: C[M,4096] = A[M,1024] * W[4096,1024]^T + bias ----------------
#define GA_STRIDE 20

__global__ __launch_bounds__(256, 2)
void gemm_xg_kernel(const float* __restrict__ A,
                    const float* __restrict__ W,
                    const float* __restrict__ b0,
                    const float* __restrict__ b1,
                    float* __restrict__ C)
{
    __shared__ float Ash[128 * GA_STRIDE];
    __shared__ float Bsh[128 * GA_STRIDE];

    const int tid  = threadIdx.x;
    const int wid  = tid >> 5, lane = tid & 31;
    const int g    = lane >> 2, t = lane & 3;
    const int wm   = wid & 1, wn = wid >> 1;
    const int cm   = blockIdx.y * 128;
    const int cn   = blockIdx.x * 128;

    float acc[4][4][4];
    #pragma unroll
    for (int i = 0; i < 4; i++)
        #pragma unroll
        for (int j = 0; j < 4; j++)
            #pragma unroll
            for (int q = 0; q < 4; q++) acc[i][j][q] = 0.0f;

    const int r0 = tid >> 2;
    const int q0 = tid & 3;

    const float* Ag = A + (size_t)cm * 1024;
    const float* Bg = W + (size_t)cn * 1024;

    for (int kk = 0; kk < 1024; kk += 16) {
        float4 av0 = *(const float4*)(Ag + (size_t)r0 * 1024 + kk + 4 * q0);
        float4 av1 = *(const float4*)(Ag + (size_t)(r0 + 64) * 1024 + kk + 4 * q0);
        float4 bv0 = *(const float4*)(Bg + (size_t)r0 * 1024 + kk + 4 * q0);
        float4 bv1 = *(const float4*)(Bg + (size_t)(r0 + 64) * 1024 + kk + 4 * q0);
        __syncthreads();
        {
            float4 w;
            w.x = f2tf32(av0.x); w.y = f2tf32(av0.y); w.z = f2tf32(av0.z); w.w = f2tf32(av0.w);
            *(float4*)(Ash + r0 * GA_STRIDE + 4 * q0) = w;
            w.x = f2tf32(av1.x); w.y = f2tf32(av1.y); w.z = f2tf32(av1.z); w.w = f2tf32(av1.w);
            *(float4*)(Ash + (r0 + 64) * GA_STRIDE + 4 * q0) = w;
            w.x = f2tf32(bv0.x); w.y = f2tf32(bv0.y); w.z = f2tf32(bv0.z); w.w = f2tf32(bv0.w);
            *(float4*)(Bsh + r0 * GA_STRIDE + 4 * q0) = w;
            w.x = f2tf32(bv1.x); w.y = f2tf32(bv1.y); w.z = f2tf32(bv1.z); w.w = f2tf32(bv1.w);
            *(float4*)(Bsh + (r0 + 64) * GA_STRIDE + 4 * q0) = w;
        }
        __syncthreads();

        #pragma unroll
        for (int kc = 0; kc < 16; kc += 8) {
            uint32_t af[4][4];
            uint32_t bf[4][2];
            #pragma unroll
            for (int mt = 0; mt < 4; mt++) {
                int rb = wm * 64 + mt * 16;
                af[mt][0] = __float_as_uint(Ash[(rb + g)     * GA_STRIDE + kc + t]);
                af[mt][1] = __float_as_uint(Ash[(rb + g + 8) * GA_STRIDE + kc + t]);
                af[mt][2] = __float_as_uint(Ash[(rb + g)     * GA_STRIDE + kc + t + 4]);
                af[mt][3] = __float_as_uint(Ash[(rb + g + 8) * GA_STRIDE + kc + t + 4]);
            }
            #pragma unroll
            for (int nt = 0; nt < 4; nt++) {
                int nb = wn * 32 + nt * 8 + g;
                bf[nt][0] = __float_as_uint(Bsh[nb * GA_STRIDE + kc + t]);
                bf[nt][1] = __float_as_uint(Bsh[nb * GA_STRIDE + kc + t + 4]);
            }
            #pragma unroll
            for (int mt = 0; mt < 4; mt++)
                #pragma unroll
                for (int nt = 0; nt < 4; nt++)
                    mma_tf32(acc[mt][nt][0], acc[mt][nt][1], acc[mt][nt][2], acc[mt][nt][3],
                             af[mt][0], af[mt][1], af[mt][2], af[mt][3],
                             bf[nt][0], bf[nt][1]);
        }
    }

    #pragma unroll
    for (int mt = 0; mt < 4; mt++) {
        #pragma unroll
        for (int nt = 0; nt < 4; nt++) {
            int m = cm + wm * 64 + mt * 16 + g;
            int n = cn + wn * 32 + nt * 8 + 2 * t;
            float bs0 = b0[n] + b1[n];
            float bs1 = b0[n + 1] + b1[n + 1];
            float2 v0 = make_float2(acc[mt][nt][0] + bs0, acc[mt][nt][1] + bs1);
            float2 v1 = make_float2(acc[mt][nt][2] + bs0, acc[mt][nt][3] + bs1);
            *(float2*)(C + (size_t)m * G4_ + n) = v0;
            *(float2*)(C + (size_t)(m + 8) * G4_ + n) = v1;
        }
    }
}

// ---------------- persistent LSTM scan ----------------
// 128 blocks x 512 threads. Block b owns gate-cols {gate*1024 + b*8 + j}, j in [0,8).
// Output tile per block/step: 32 batch x 32 gate-cols, K=1024.
// 16 warps, warp = one K-slice of 64 (8 ksteps), covering all 32 cols (4 ntiles)
// and all 32 batch (2 mtiles). A (=h) loaded as coalesced LDG.128 from the
// frag-permuted gmem buffer; W (=B frags) from frag-permuted smem (LDS.64,
// conflict-free). 16-way K reduction through padded smem (stride 40: both store
// and reduce provably bank-conflict-free).
#define WS_  32768                 // W frag floats: 16ks*8s*4nt*32lane*2
#define RSTR 40
#define RS_  (16 * 32 * RSTR)      // reduction buffer floats
#define SCAN_SMEM ((WS_ + RS_) * 4)   // 131072 + 81920 = 212992 B

__global__ __launch_bounds__(NTHR, 1)
void lstm_scan_kernel(const float* __restrict__ xg,     // [M, 4096]
                      const float* __restrict__ Whh,    // [4096, 1024]
                      const float* __restrict__ resid,  // [M, 1024] or nullptr
                      float* __restrict__ outseq)       // [M, 1024]
{
    extern __shared__ float sm[];
    float* Wsh = sm;            // WS_ floats
    float* Rsh = sm + WS_;      // RS_ floats

    const int tid  = threadIdx.x;
    const int bid  = blockIdx.x;
    const int wid  = tid >> 5, lane = tid & 31;
    const int g    = lane >> 2, t = lane & 3;
    const int ks   = wid;                 // 0..15, K-slice of 64

    // ---- fill W frags into shared (tf32-rounded), frag-permuted ----
    // index e = (((ks*8 + s)*4 + nt)*32 + lane)*2 + rr
    for (int e = tid; e < WS_; e += NTHR) {
        int rr = e & 1;
        int ln = (e >> 1) & 31;
        int nt = (e >> 6) & 3;
        int s  = (e >> 8) & 7;
        int kk = e >> 11;
        int n8 = ln >> 2, tt = ln & 3;
        int j32  = nt * 8 + n8;                              // 0..31
        int wrow = (j32 >> 3) * 1024 + bid * 8 + (j32 & 7);  // Whh row (gate-major)
        int k    = kk * 64 + s * 8 + tt + rr * 4;
        Wsh[e] = f2tf32(Whh[(size_t)wrow * 1024 + k]);
    }

    // elementwise ownership (tid < 256): (batch b, local col j)
    const int eb   = tid >> 3;
    const int ej   = tid & 7;
    const int hcol = bid * 8 + ej;
    // frag-permuted offset for h element (eb, hcol): s = bid
    const int fmt  = eb >> 4;
    const int foff = (((bid * 2 + fmt) * 32 + (eb & 7) * 4 + (ej & 3)) << 2)
                     + ((eb >> 3) & 1) + ((ej >> 2) << 1);

    if (tid < 256) g_hA[0][foff] = 0.0f;
    float c_state = 0.0f;

    unsigned phase = 1;
    grid_barrier(phase * NBLK);

    int p = 0;
    for (int ts = 0; ts < T_; ts++) {
        // prefetch xg + residual (independent of h; hides DRAM latency)
        float xv0 = 0.f, xv1 = 0.f, xv2 = 0.f, xv3 = 0.f, rv = 0.f;
        size_t mrow = 0;
        if (tid < 256) {
            mrow = (size_t)eb * T_ + ts;
            const float* xp = xg + mrow * G4_ + hcol;
            xv0 = __ldcs(xp);
            xv1 = __ldcs(xp + 1024);
            xv2 = __ldcs(xp + 2048);
            xv3 = __ldcs(xp + 3072);
            if (resid) rv = __ldcs(resid + mrow * H_ + hcol);
        }

        float acc[2][4][4];
        #pragma unroll
        for (int mt = 0; mt < 2; mt++)
            #pragma unroll
            for (int nt = 0; nt < 4; nt++)
                #pragma unroll
                for (int q = 0; q < 4; q++) acc[mt][nt][q] = 0.0f;

        const float4* hA = (const float4*)g_hA[p];
        #pragma unroll
        for (int si = 0; si < 8; si++) {
            int s = ks * 8 + si;
            float4 a0 = __ldcg(hA + (s * 2 + 0) * 32 + lane);
            float4 a1 = __ldcg(hA + (s * 2 + 1) * 32 + lane);
            #pragma unroll
            for (int nt = 0; nt < 4; nt++) {
                float2 w = *(const float2*)(Wsh + (((((ks * 8 + si) * 4) + nt) * 32 + lane) << 1));
                mma_tf32(acc[0][nt][0], acc[0][nt][1], acc[0][nt][2], acc[0][nt][3],
                         __float_as_uint(a0.x), __float_as_uint(a0.y),
                         __float_as_uint(a0.z), __float_as_uint(a0.w),
                         __float_as_uint(w.x), __float_as_uint(w.y));
                mma_tf32(acc[1][nt][0], acc[1][nt][1], acc[1][nt][2], acc[1][nt][3],
                         __float_as_uint(a1.x), __float_as_uint(a1.y),
                         __float_as_uint(a1.z), __float_as_uint(a1.w),
                         __float_as_uint(w.x), __float_as_uint(w.y));
            }
        }

        // store K-partials to Rsh (conflict-free per 16-lane phase)
        #pragma unroll
        for (int mt = 0; mt < 2; mt++) {
            #pragma unroll
            for (int nt = 0; nt < 4; nt++) {
                int row = mt * 16 + g;
                int col = nt * 8 + 2 * t;
                *(float2*)(Rsh + (ks * 32 + row) * RSTR + col) =
                    make_float2(acc[mt][nt][0], acc[mt][nt][1]);
                *(float2*)(Rsh + (ks * 32 + row + 8) * RSTR + col) =
                    make_float2(acc[mt][nt][2], acc[mt][nt][3]);
            }
        }
        __syncthreads();

        // 16-way reduce + LSTM cell (256 active threads)
        if (tid < 256) {
            float s0 = xv0, s1 = xv1, s2 = xv2, s3 = xv3;
            #pragma unroll
            for (int kk = 0; kk < 16; kk++) {
                const float* rp = Rsh + (kk * 32 + eb) * RSTR + ej;
                s0 += rp[0];
                s1 += rp[8];
                s2 += rp[16];
                s3 += rp[24];
            }
            float iv = sigm(s0);
            float fv = sigm(s1);
            float gv = tanhf(s2);
            float ov = sigm(s3);
            c_state = fv * c_state + iv * gv;
            float hval = ov * tanhf(c_state);

            g_hA[1 - p][foff] = f2tf32(hval);          // frag-permuted recurrent copy
            outseq[mrow * H_ + hcol] = hval + rv;      // normal-layout output (+residual)
        }

        phase++;
        grid_barrier(phase * NBLK);
        p ^= 1;
    }
}

// ---------------- launch ----------------
extern "C" void kernel_launch(void* const* d_in, const int* in_sizes, int n_in,
                              void* d_out, int out_size) {
    const float* x    = (const float*)d_in[0];
    const float* Wih0 = (const float*)d_in[1];
    const float* Whh0 = (const float*)d_in[2];
    const float* bih0 = (const float*)d_in[3];
    const float* bhh0 = (const float*)d_in[4];
    const float* Wih1 = (const float*)d_in[5];
    const float* Whh1 = (const float*)d_in[6];
    const float* bih1 = (const float*)d_in[7];
    const float* bhh1 = (const float*)d_in[8];
    float* out = (float*)d_out;

    cudaFuncSetAttribute(lstm_scan_kernel,
                         cudaFuncAttributeMaxDynamicSharedMemorySize, SCAN_SMEM);

    void* p;
    cudaGetSymbolAddress(&p, g_xg);     float* xg = (float*)p;
    cudaGetSymbolAddress(&p, g_h0seq);  float* h0 = (float*)p;
    cudaGetSymbolAddress(&p, g_arrive); unsigned* arr = (unsigned*)p;

    dim3 gg(32, 128);  // (N tiles, M tiles)

    // layer 0
    cudaMemsetAsync(arr, 0, sizeof(unsigned));
    gemm_xg_kernel<<<gg, 256>>>(x, Wih0, bih0, bhh0, xg);
    lstm_scan_kernel<<<NBLK, NTHR, SCAN_SMEM>>>(xg, Whh0, nullptr, h0);
    // layer 1 (+ residual into final out)
    cudaMemsetAsync(arr, 0, sizeof(unsigned));
    gemm_xg_kernel<<<gg, 256>>>(h0, Wih1, bih1, bhh1, xg);
    lstm_scan_kernel<<<NBLK, NTHR, SCAN_SMEM>>>(xg, Whh1, h0, out);
}